// round 1
// baseline (speedup 1.0000x reference)
#include <cuda_runtime.h>
#include <cuda_bf16.h>

// out[8192,4096] = x[8192,4096] @ W[4096,4096] + bias[4096]   (all fp32)
//
// Baseline: SIMT fp32 tiled GEMM.
//   Block tile: 128 (M) x 128 (N), K-tile 16
//   256 threads, each computes an 8x8 micro-tile.
//   A staged transposed in smem (As[k][m]), B staged as Bs[k][n].
//   Vectorized float4 global loads; no boundary guards (all dims divide evenly).

#define TOKENS 8192
#define SIZE_IN 4096
#define SIZE_OUT 4096

#define BM 128
#define BN 128
#define BK 16
#define TM 8
#define TN 8
#define THREADS 256

// As padded to 132 floats per row: keeps rows 16B-aligned for float4 fragment
// loads while de-phasing the k-strided scalar stores across banks.
#define AS_STRIDE 132
#define BS_STRIDE 128

__global__ __launch_bounds__(THREADS, 2)
void positlinear_gemm_kernel(const float* __restrict__ A,   // [TOKENS, SIZE_IN]
                             const float* __restrict__ B,   // [SIZE_IN, SIZE_OUT]
                             const float* __restrict__ bias,// [SIZE_OUT]
                             float* __restrict__ C)         // [TOKENS, SIZE_OUT]
{
    __shared__ float As[BK][AS_STRIDE];
    __shared__ float Bs[BK][BS_STRIDE];

    const int tid = threadIdx.x;
    const int tx = tid % 16;           // column group (N)
    const int ty = tid / 16;           // row group (M)

    const int bm = blockIdx.y * BM;
    const int bn = blockIdx.x * BN;

    // ---- A load mapping: 128 rows x 16 cols = 512 float4; 2 per thread ----
    const int aRow = tid / 4;          // 0..63  (rows aRow and aRow+64)
    const int aK4  = (tid % 4) * 4;    // float4 column start within BK

    // ---- B load mapping: 16 rows x 128 cols = 512 float4; 2 per thread ----
    const int bRow0 = tid / 32;        // 0..7   (rows bRow0 and bRow0+8)
    const int bCol4 = (tid % 32) * 4;  // float4 column start within BN

    float acc[TM][TN];
    #pragma unroll
    for (int i = 0; i < TM; i++)
        #pragma unroll
        for (int j = 0; j < TN; j++)
            acc[i][j] = 0.0f;

    const float* Aptr = A + (long long)bm * SIZE_IN;
    const float* Bptr = B + bn;

    for (int kt = 0; kt < SIZE_IN; kt += BK) {
        // Stage A tile, transposed: As[k][m]
        #pragma unroll
        for (int r = 0; r < 2; r++) {
            int m = aRow + r * 64;
            float4 v = *reinterpret_cast<const float4*>(
                Aptr + (long long)m * SIZE_IN + kt + aK4);
            As[aK4 + 0][m] = v.x;
            As[aK4 + 1][m] = v.y;
            As[aK4 + 2][m] = v.z;
            As[aK4 + 3][m] = v.w;
        }
        // Stage B tile: Bs[k][n]
        #pragma unroll
        for (int r = 0; r < 2; r++) {
            int k = bRow0 + r * 8;
            float4 v = *reinterpret_cast<const float4*>(
                Bptr + (long long)(kt + k) * SIZE_OUT + bCol4);
            *reinterpret_cast<float4*>(&Bs[k][bCol4]) = v;
        }
        __syncthreads();

        #pragma unroll
        for (int k = 0; k < BK; k++) {
            float afrag[TM], bfrag[TN];
            #pragma unroll
            for (int i = 0; i < TM; i += 4) {
                float4 v = *reinterpret_cast<const float4*>(&As[k][ty * TM + i]);
                afrag[i + 0] = v.x; afrag[i + 1] = v.y;
                afrag[i + 2] = v.z; afrag[i + 3] = v.w;
            }
            #pragma unroll
            for (int j = 0; j < TN; j += 4) {
                float4 v = *reinterpret_cast<const float4*>(&Bs[k][tx * TN + j]);
                bfrag[j + 0] = v.x; bfrag[j + 1] = v.y;
                bfrag[j + 2] = v.z; bfrag[j + 3] = v.w;
            }
            #pragma unroll
            for (int i = 0; i < TM; i++)
                #pragma unroll
                for (int j = 0; j < TN; j++)
                    acc[i][j] = fmaf(afrag[i], bfrag[j], acc[i][j]);
        }
        __syncthreads();
    }

    // Epilogue: add bias, vectorized float4 stores
    #pragma unroll
    for (int i = 0; i < TM; i++) {
        int row = bm + ty * TM + i;
        #pragma unroll
        for (int j = 0; j < TN; j += 4) {
            int col = bn + tx * TN + j;
            float4 bv = *reinterpret_cast<const float4*>(bias + col);
            float4 o;
            o.x = acc[i][j + 0] + bv.x;
            o.y = acc[i][j + 1] + bv.y;
            o.z = acc[i][j + 2] + bv.z;
            o.w = acc[i][j + 3] + bv.w;
            *reinterpret_cast<float4*>(C + (long long)row * SIZE_OUT + col) = o;
        }
    }
}

extern "C" void kernel_launch(void* const* d_in, const int* in_sizes, int n_in,
                              void* d_out, int out_size) {
    const float* x    = (const float*)d_in[0];   // [8192, 4096]
    const float* w    = (const float*)d_in[1];   // [4096, 4096]
    const float* bias = (const float*)d_in[2];   // [4096]
    float* out = (float*)d_out;                  // [8192, 4096]

    dim3 grid(SIZE_OUT / BN, TOKENS / BM);       // (32, 64)
    dim3 block(THREADS);
    positlinear_gemm_kernel<<<grid, block>>>(x, w, bias, out);
}

// round 3
// speedup vs baseline: 2.5041x; 2.5041x over previous
#include <cuda_runtime.h>
#include <cuda_bf16.h>
#include <cstdint>

// out[8192,4096] = x[8192,4096] @ W[4096,4096] + bias[4096]  (fp32)
//
// bf16 split GEMM on warp-level mma.sync (sm_80+ baseline PTX; no tcgen05,
// which the harness's plain-sm_103 ptxas target rejects):
//   C = Ah*Bh + Ah*Bl + Al*Bh   (fp32 accumulate, al*bl dropped ~2^-16)
// CTA tile 128x128, K-stage 32, double-buffered smem, on-the-fly fp32->bf16
// hi/lo conversion, ldmatrix + mma.sync.m16n8k16.

#define TOKENS 8192
#define SIZE_IN 4096
#define SIZE_OUT 4096

#define BM 128
#define BN 128
#define BK 32
#define NK (SIZE_IN / BK)         // 128 stages
#define THREADS 256

// smem strides (bytes), padded for conflict-free ldmatrix
#define A_STRIDE 80               // 32 bf16 = 64B + 16B pad
#define B_STRIDE 272              // 128 bf16 = 256B + 16B pad
#define AS_BYTES (128 * A_STRIDE) // 10240
#define BS_BYTES (32 * B_STRIDE)  // 8704
#define OFF_A_HI 0
#define OFF_A_LO AS_BYTES
#define OFF_B_HI (2 * AS_BYTES)
#define OFF_B_LO (2 * AS_BYTES + BS_BYTES)
#define STAGE_BYTES (2 * AS_BYTES + 2 * BS_BYTES)  // 37888
#define SMEM_TOTAL (2 * STAGE_BYTES)               // 75776

__device__ __forceinline__ uint32_t smem_u32(const void* p) {
    uint32_t a;
    asm("{ .reg .u64 t; cvta.to.shared.u64 t, %1; cvt.u32.u64 %0, t; }" : "=r"(a) : "l"(p));
    return a;
}

__device__ __forceinline__ void ldm_x4(uint32_t (&r)[4], uint32_t addr) {
    asm volatile("ldmatrix.sync.aligned.m8n8.x4.shared.b16 {%0,%1,%2,%3}, [%4];"
                 : "=r"(r[0]), "=r"(r[1]), "=r"(r[2]), "=r"(r[3]) : "r"(addr));
}
__device__ __forceinline__ void ldm_x4_t(uint32_t (&r)[4], uint32_t addr) {
    asm volatile("ldmatrix.sync.aligned.m8n8.x4.trans.shared.b16 {%0,%1,%2,%3}, [%4];"
                 : "=r"(r[0]), "=r"(r[1]), "=r"(r[2]), "=r"(r[3]) : "r"(addr));
}
__device__ __forceinline__ void mma_bf16(float (&c)[4], const uint32_t (&a)[4],
                                         uint32_t b0, uint32_t b1) {
    asm volatile(
        "mma.sync.aligned.m16n8k16.row.col.f32.bf16.bf16.f32 "
        "{%0,%1,%2,%3}, {%4,%5,%6,%7}, {%8,%9}, {%0,%1,%2,%3};"
        : "+f"(c[0]), "+f"(c[1]), "+f"(c[2]), "+f"(c[3])
        : "r"(a[0]), "r"(a[1]), "r"(a[2]), "r"(a[3]), "r"(b0), "r"(b1));
}

// fp32x4 -> (hi bf16x4, lo bf16x4) packed as uint2 each
__device__ __forceinline__ void split4(float4 v, uint2& hi, uint2& lo) {
    __nv_bfloat162 h01 = __float22bfloat162_rn(make_float2(v.x, v.y));
    __nv_bfloat162 h23 = __float22bfloat162_rn(make_float2(v.z, v.w));
    float2 f01 = __bfloat1622float2(h01);
    float2 f23 = __bfloat1622float2(h23);
    __nv_bfloat162 l01 = __float22bfloat162_rn(make_float2(v.x - f01.x, v.y - f01.y));
    __nv_bfloat162 l23 = __float22bfloat162_rn(make_float2(v.z - f23.x, v.w - f23.y));
    hi.x = *reinterpret_cast<uint32_t*>(&h01);
    hi.y = *reinterpret_cast<uint32_t*>(&h23);
    lo.x = *reinterpret_cast<uint32_t*>(&l01);
    lo.y = *reinterpret_cast<uint32_t*>(&l23);
}

__global__ __launch_bounds__(THREADS, 1)
void gemm_kernel(const float* __restrict__ A,    // [8192, 4096]
                 const float* __restrict__ B,    // [4096, 4096]
                 const float* __restrict__ bias, // [4096]
                 float* __restrict__ C)          // [8192, 4096]
{
    extern __shared__ unsigned char smem[];

    const int tid  = threadIdx.x;
    const int lane = tid & 31;
    const int wid  = tid >> 5;
    const int wm   = wid & 3;   // warp M index (4 warps * 32 rows)
    const int wn   = wid >> 2;  // warp N index (2 warps * 64 cols)

    // CTA raster: groups of 8 m-tiles per n sweep for L2 reuse
    const int pid = blockIdx.x;                 // 0..2047
    const int NPG = 8 * (SIZE_OUT / BN);        // 256
    const int gid = pid / NPG;
    const int mt  = gid * 8 + (pid % NPG) % 8;
    const int nt  = (pid % NPG) / 8;
    const int bm  = mt * BM;
    const int bn  = nt * BN;

    // ---- global load mapping ----
    const int arow = tid >> 3;         // 0..31 (rows arow + i*32)
    const int af   = tid & 7;          // float4 index within 32-wide k
    const int brow = tid >> 5;         // 0..7  (k-rows brow + i*8)
    const int bc   = tid & 31;         // float4 index within 128-wide n

    const float* Ab = A + (size_t)bm * SIZE_IN;
    const float* Bb = B + bn;

    float4 ra[4], rb[4];

    auto ldg_stage = [&](int k0) {
#pragma unroll
        for (int i = 0; i < 4; i++)
            ra[i] = *reinterpret_cast<const float4*>(
                Ab + (size_t)(arow + i * 32) * SIZE_IN + k0 + af * 4);
#pragma unroll
        for (int i = 0; i < 4; i++)
            rb[i] = *reinterpret_cast<const float4*>(
                Bb + (size_t)(k0 + brow + i * 8) * SIZE_OUT + bc * 4);
    };

    auto sts_stage = [&](int s) {
        unsigned char* base = smem + s * STAGE_BYTES;
#pragma unroll
        for (int i = 0; i < 4; i++) {
            uint2 hi, lo;
            split4(ra[i], hi, lo);
            uint32_t off = (arow + i * 32) * A_STRIDE + af * 8;
            *reinterpret_cast<uint2*>(base + OFF_A_HI + off) = hi;
            *reinterpret_cast<uint2*>(base + OFF_A_LO + off) = lo;
        }
#pragma unroll
        for (int i = 0; i < 4; i++) {
            uint2 hi, lo;
            split4(rb[i], hi, lo);
            uint32_t off = (brow + i * 8) * B_STRIDE + bc * 8;
            *reinterpret_cast<uint2*>(base + OFF_B_HI + off) = hi;
            *reinterpret_cast<uint2*>(base + OFF_B_LO + off) = lo;
        }
    };

    // ---- ldmatrix lane addressing ----
    const uint32_t sb0 = smem_u32(smem);
    const int qrow = (lane & 7) + 8 * ((lane >> 3) & 1);
    const int kq   = (lane >> 4) * 8;

    float acc[2][8][4];
#pragma unroll
    for (int i = 0; i < 2; i++)
#pragma unroll
        for (int j = 0; j < 8; j++)
#pragma unroll
            for (int k = 0; k < 4; k++) acc[i][j][k] = 0.0f;

    auto compute_stage = [&](int s) {
        uint32_t sbase = sb0 + s * STAGE_BYTES;
#pragma unroll
        for (int ks = 0; ks < BK; ks += 16) {
            uint32_t ah[2][4], al[2][4];
#pragma unroll
            for (int m2 = 0; m2 < 2; m2++) {
                uint32_t ad = sbase + (wm * 32 + m2 * 16 + qrow) * A_STRIDE
                            + (ks + kq) * 2;
                ldm_x4(ah[m2], ad + OFF_A_HI);
                ldm_x4(al[m2], ad + OFF_A_LO);
            }
            uint32_t bh[4][4], bl[4][4];
#pragma unroll
            for (int n16 = 0; n16 < 4; n16++) {
                uint32_t bd = sbase + (ks + qrow) * B_STRIDE
                            + (wn * 64 + n16 * 16 + kq) * 2;
                ldm_x4_t(bh[n16], bd + OFF_B_HI);
                ldm_x4_t(bl[n16], bd + OFF_B_LO);
            }
#pragma unroll
            for (int m2 = 0; m2 < 2; m2++)
#pragma unroll
                for (int n16 = 0; n16 < 4; n16++)
#pragma unroll
                    for (int h = 0; h < 2; h++) {
                        int n8 = n16 * 2 + h;
                        mma_bf16(acc[m2][n8], ah[m2], bh[n16][2*h], bh[n16][2*h+1]);
                        mma_bf16(acc[m2][n8], ah[m2], bl[n16][2*h], bl[n16][2*h+1]);
                        mma_bf16(acc[m2][n8], al[m2], bh[n16][2*h], bh[n16][2*h+1]);
                    }
        }
    };

    // ---- pipeline ----
    ldg_stage(0);
    sts_stage(0);
    __syncthreads();

    for (int kt = 0; kt < NK; kt++) {
        if (kt + 1 < NK) ldg_stage((kt + 1) * BK);
        compute_stage(kt & 1);
        if (kt + 1 < NK) sts_stage((kt + 1) & 1);
        __syncthreads();
    }

    // ---- epilogue: bias add + store ----
    const int crow0 = bm + wm * 32 + (lane >> 2);
    const int ccol0 = bn + wn * 64 + (lane & 3) * 2;
#pragma unroll
    for (int m2 = 0; m2 < 2; m2++) {
#pragma unroll
        for (int n8 = 0; n8 < 8; n8++) {
            int col = ccol0 + n8 * 8;
            float2 bv = *reinterpret_cast<const float2*>(bias + col);
            int r0 = crow0 + m2 * 16;
            float2 o0 = { acc[m2][n8][0] + bv.x, acc[m2][n8][1] + bv.y };
            float2 o1 = { acc[m2][n8][2] + bv.x, acc[m2][n8][3] + bv.y };
            *reinterpret_cast<float2*>(C + (size_t)r0 * SIZE_OUT + col) = o0;
            *reinterpret_cast<float2*>(C + (size_t)(r0 + 8) * SIZE_OUT + col) = o1;
        }
    }
}

extern "C" void kernel_launch(void* const* d_in, const int* in_sizes, int n_in,
                              void* d_out, int out_size) {
    const float* x    = (const float*)d_in[0];   // [8192, 4096]
    const float* w    = (const float*)d_in[1];   // [4096, 4096]
    const float* bias = (const float*)d_in[2];   // [4096]
    float* out = (float*)d_out;                  // [8192, 4096]

    cudaFuncSetAttribute(gemm_kernel, cudaFuncAttributeMaxDynamicSharedMemorySize,
                         SMEM_TOTAL);
    gemm_kernel<<<(TOKENS / BM) * (SIZE_OUT / BN), THREADS, SMEM_TOTAL>>>(
        x, w, bias, out);
}